// round 12
// baseline (speedup 1.0000x reference)
#include <cuda_runtime.h>
#include <cuda_fp16.h>
#include <math.h>

typedef unsigned int u32;
typedef unsigned long long u64;

#define NLEV 16
#define HSIZE (1u << 19)
#define HMASK (HSIZE - 1u)
#define NPTS (4096 * 128)
#define NCHUNK 2
#define CPTS (NPTS / NCHUNK)

struct Consts { float res[NLEV]; };

// 67 MB scratch: per-level encoded features, feat-major for coalescing.
__device__ float2 g_enc[NLEV * NPTS];

// ---------- packed f32x2 helpers ----------
__device__ __forceinline__ u64 pk2(float a, float b) {
    u64 r; asm("mov.b64 %0,{%1,%2};" : "=l"(r) : "f"(a), "f"(b)); return r;
}
__device__ __forceinline__ void up2(u64 v, float& a, float& b) {
    asm("mov.b64 {%0,%1},%2;" : "=f"(a), "=f"(b) : "l"(v));
}
__device__ __forceinline__ u64 f2fma(u64 a, u64 b, u64 c) {
    u64 d; asm("fma.rn.f32x2 %0,%1,%2,%3;" : "=l"(d) : "l"(a), "l"(b), "l"(c)); return d;
}

// ===================== K1: encode (gather-bound) =====================

__device__ __forceinline__ void level_fetch(
    float px, float py, float pz, float r,
    const float2* __restrict__ tab,
    float2 tv[8], float& ax, float& ay, float& az)
{
    const float X = px * r, Y = py * r, Z = pz * r;
    const float fx = floorf(X), fy = floorf(Y), fz = floorf(Z);
    ax = X - fx; ay = Y - fy; az = Z - fz;
    const u32 ix = (u32)fx, iy = (u32)fy, iz = (u32)fz;
    const u32 hx0 = ix, hx1 = ix + 1u;
    const u32 hy0 = iy * 2654435761u, hy1 = hy0 + 2654435761u;
    const u32 hz0 = iz * 805459861u,  hz1 = hz0 + 805459861u;
    #pragma unroll
    for (int c = 0; c < 8; c++) {
        const u32 hx = (c & 4) ? hx1 : hx0;
        const u32 hy = (c & 2) ? hy1 : hy0;
        const u32 hz = (c & 1) ? hz1 : hz0;
        tv[c] = __ldg(tab + ((hx ^ hy ^ hz) & HMASK));
    }
}

__global__ void __launch_bounds__(256, 4) encode_kernel(
    const float* __restrict__ xyz, const float* __restrict__ table, Consts cc,
    int base)
{
    const int p = base + blockIdx.x * 256 + threadIdx.x;
    const float px = __ldg(xyz + 3 * p);
    const float py = __ldg(xyz + 3 * p + 1);
    const float pz = __ldg(xyz + 3 * p + 2);

    float2 tvb[2][8];
    float fr[2][3];
    level_fetch(px, py, pz, cc.res[0], (const float2*)table,
                tvb[0], fr[0][0], fr[0][1], fr[0][2]);

    #pragma unroll 2
    for (int l = 0; l < NLEV; l++) {
        const int cur = l & 1, nxt = cur ^ 1;
        if (l + 1 < NLEV)
            level_fetch(px, py, pz, cc.res[l + 1],
                        (const float2*)table + (size_t)(l + 1) * HSIZE,
                        tvb[nxt], fr[nxt][0], fr[nxt][1], fr[nxt][2]);
        const float ax = fr[cur][0], ay = fr[cur][1], az = fr[cur][2];
        const float bx = 1.f - ax, by = 1.f - ay, bz = 1.f - az;
        float a0 = 0.f, a1 = 0.f;
        #pragma unroll
        for (int c = 0; c < 8; c++) {
            const float w = ((c & 4) ? ax : bx) * ((c & 2) ? ay : by) * ((c & 1) ? az : bz);
            a0 = fmaf(w, tvb[cur][c].x, a0);
            a1 = fmaf(w, tvb[cur][c].y, a1);
        }
        g_enc[l * NPTS + p] = make_float2(a0, a1);
    }
}

// ===================== K2: MLP + volrend (FMA-bound target) =====================

#define OFF_WIN  0
#define OFF_WOUT 2048
#define OFF_W1   3072
#define OFF_W2   4032
#define OFF_W3   8128
#define OFF_FA   8320                 // feats ray A: 128 rows x 17
#define OFF_FB   (8320 + 128 * 17)
#define SMEM_FLOATS (8320 + 2 * 128 * 17)
#define SMEM_BYTES (SMEM_FLOATS * 4)

__global__ void __launch_bounds__(128, 4) mlp_kernel(
    const float* __restrict__ delta,
    const float* __restrict__ w_in, const float* __restrict__ w_out,
    const float* __restrict__ rw1, const float* __restrict__ rw2,
    const float* __restrict__ rw3, float4* __restrict__ out, float offset,
    int base)
{
    extern __shared__ float dsm[];
    __shared__ float wsumA[4], wsumB[4];
    const int t = threadIdx.x;
    for (int i = t; i < 8320; i += 128) {
        float v;
        if (i < 2048)      v = w_in[i];
        else if (i < 3072) v = w_out[i - 2048];
        else if (i < 4032) v = rw1[i - 3072];
        else if (i < 8128) v = rw2[i - 4032];
        else               v = rw3[i - 8128];
        dsm[i] = v;
    }
    __syncthreads();

    const int pA = base + blockIdx.x * 256 + t;   // ray A
    const int pB = pA + 128;                      // ray B
    float* FA = dsm + OFF_FA + t * 17;
    float* FB = dsm + OFF_FB + t * 17;

    // ---- density MLP: two passes over hidden-halves ----
    u64 rA2[8], rB2[8];
    #pragma unroll
    for (int j = 0; j < 8; j++) { rA2[j] = 0ULL; rB2[j] = 0ULL; }

    #pragma unroll 1
    for (int half = 0; half < 2; half++) {
        u64 hA[16], hB[16];
        #pragma unroll
        for (int j = 0; j < 16; j++) { hA[j] = 0ULL; hB[j] = 0ULL; }

        #pragma unroll 1
        for (int l = 0; l < NLEV; l++) {
            const float2 eA = g_enc[l * NPTS + pA];
            const float2 eB = g_enc[l * NPTS + pB];
            const u64 e0A = pk2(eA.x, eA.x), e1A = pk2(eA.y, eA.y);
            const u64 e0B = pk2(eB.x, eB.x), e1B = pk2(eB.y, eB.y);
            const u64* r0 = (const u64*)(dsm + OFF_WIN + (2 * l) * 64 + half * 32);
            const u64* r1 = r0 + 32;
            #pragma unroll
            for (int j = 0; j < 16; j += 2) {
                const ulonglong2 wv0 = *(const ulonglong2*)(r0 + j);
                const ulonglong2 wv1 = *(const ulonglong2*)(r1 + j);
                hA[j]     = f2fma(e1A, wv1.x, f2fma(e0A, wv0.x, hA[j]));
                hA[j + 1] = f2fma(e1A, wv1.y, f2fma(e0A, wv0.y, hA[j + 1]));
                hB[j]     = f2fma(e1B, wv1.x, f2fma(e0B, wv0.x, hB[j]));
                hB[j + 1] = f2fma(e1B, wv1.y, f2fma(e0B, wv0.y, hB[j + 1]));
            }
        }

        #pragma unroll
        for (int ic = 0; ic < 16; ic++) {
            float vA0, vA1, vB0, vB1;
            up2(hA[ic], vA0, vA1); up2(hB[ic], vB0, vB1);
            const u64 e0A = pk2(fmaxf(vA0, 0.f), fmaxf(vA0, 0.f));
            const u64 e1A = pk2(fmaxf(vA1, 0.f), fmaxf(vA1, 0.f));
            const u64 e0B = pk2(fmaxf(vB0, 0.f), fmaxf(vB0, 0.f));
            const u64 e1B = pk2(fmaxf(vB1, 0.f), fmaxf(vB1, 0.f));
            const u64* r0 = (const u64*)(dsm + OFF_WOUT + (half * 32 + 2 * ic) * 16);
            const u64* r1 = r0 + 8;
            #pragma unroll
            for (int j = 0; j < 8; j += 2) {
                const ulonglong2 wv0 = *(const ulonglong2*)(r0 + j);
                const ulonglong2 wv1 = *(const ulonglong2*)(r1 + j);
                rA2[j]     = f2fma(e1A, wv1.x, f2fma(e0A, wv0.x, rA2[j]));
                rA2[j + 1] = f2fma(e1A, wv1.y, f2fma(e0A, wv0.y, rA2[j + 1]));
                rB2[j]     = f2fma(e1B, wv1.x, f2fma(e0B, wv0.x, rB2[j]));
                rB2[j + 1] = f2fma(e1B, wv1.y, f2fma(e0B, wv0.y, rB2[j + 1]));
            }
        }
    }

    // unpack raw: raw[0] -> density; raw[1..15] -> feats in smem rows
    float d0A = 0.f, d0B = 0.f;
    #pragma unroll
    for (int j = 0; j < 8; j++) {
        float vA0, vA1, vB0, vB1;
        up2(rA2[j], vA0, vA1); up2(rB2[j], vB0, vB1);
        const int o = 2 * j;
        if (o == 0) { d0A = vA0; d0B = vB0; }
        else { FA[o - 1] = vA0; FB[o - 1] = vB0; }
        FA[o] = vA1; FB[o] = vB1;
    }

    // ---- volume-rendering weights: block-wide exclusive scan per ray ----
    const float ddA = expf(d0A + offset + logf(__ldg(delta + pA)));
    const float ddB = expf(d0B + offset + logf(__ldg(delta + pB)));
    float sA = ddA, sB = ddB;
    const int lane = t & 31, wid = t >> 5;
    #pragma unroll
    for (int o = 1; o < 32; o <<= 1) {
        const float vA = __shfl_up_sync(0xffffffffu, sA, o);
        const float vB = __shfl_up_sync(0xffffffffu, sB, o);
        if (lane >= o) { sA += vA; sB += vB; }
    }
    if (lane == 31) { wsumA[wid] = sA; wsumB[wid] = sB; }
    __syncthreads();
    float prefA = 0.f, prefB = 0.f;
    #pragma unroll
    for (int w = 0; w < 3; w++)
        if (wid > w) { prefA += wsumA[w]; prefB += wsumB[w]; }
    const float wgtA = (1.f - expf(-ddA)) * expf(-(prefA + sA - ddA));
    const float wgtB = (1.f - expf(-ddB)) * expf(-(prefB + sB - ddB));

    // ---- rgb layer 1 in output-halves: fp32 accumulate, weights shared
    //      A+B, result packed to fp16 (h1 >= 0 after relu) ----
    u32 h1A16[32], h1B16[32];   // half2-packed h1: index ic -> (h1[2ic], h1[2ic+1])
    #pragma unroll 1
    for (int half = 0; half < 2; half++) {
        u64 gA[16], gB[16];
        #pragma unroll
        for (int j = 0; j < 16; j++) { gA[j] = 0ULL; gB[j] = 0ULL; }
        #pragma unroll 1
        for (int i = 0; i < 15; i++) {
            const float fA = FA[i], fB = FB[i];
            const u64 eA = pk2(fA, fA), eB = pk2(fB, fB);
            const u64* row = (const u64*)(dsm + OFF_W1 + i * 64 + half * 32);
            #pragma unroll
            for (int j = 0; j < 16; j += 2) {
                const ulonglong2 wv = *(const ulonglong2*)(row + j);
                gA[j]     = f2fma(eA, wv.x, gA[j]);
                gA[j + 1] = f2fma(eA, wv.y, gA[j + 1]);
                gB[j]     = f2fma(eB, wv.x, gB[j]);
                gB[j + 1] = f2fma(eB, wv.y, gB[j + 1]);
            }
        }
        #pragma unroll
        for (int j = 0; j < 16; j++) {
            float v0, v1;
            up2(gA[j], v0, v1);
            __half2 ha = __floats2half2_rn(fmaxf(v0, 0.f), fmaxf(v1, 0.f));
            h1A16[half * 16 + j] = *(u32*)&ha;
            up2(gB[j], v0, v1);
            __half2 hb = __floats2half2_rn(fmaxf(v0, 0.f), fmaxf(v1, 0.f));
            h1B16[half * 16 + j] = *(u32*)&hb;
        }
    }

    // ---- rgb layers 2+3: 8 blocks of 8 outputs, weights shared A+B ----
    float crA = 0.f, cgA = 0.f, cbA = 0.f;
    float crB = 0.f, cgB = 0.f, cbB = 0.f;
    #pragma unroll 1
    for (int ob = 0; ob < 8; ob++) {
        u64 accA[4], accB[4];
        #pragma unroll
        for (int j = 0; j < 4; j++) { accA[j] = 0ULL; accB[j] = 0ULL; }
        #pragma unroll
        for (int ic = 0; ic < 32; ic++) {
            const float2 fA2 = __half22float2(*(const __half2*)&h1A16[ic]);
            const float2 fB2 = __half22float2(*(const __half2*)&h1B16[ic]);
            const u64 e0A = pk2(fA2.x, fA2.x), e1A = pk2(fA2.y, fA2.y);
            const u64 e0B = pk2(fB2.x, fB2.x), e1B = pk2(fB2.y, fB2.y);
            const u64* r0 = (const u64*)(dsm + OFF_W2 + (2 * ic) * 64 + ob * 8);
            const u64* r1 = r0 + 32;
            #pragma unroll
            for (int j = 0; j < 4; j += 2) {
                const ulonglong2 wv0 = *(const ulonglong2*)(r0 + j);
                const ulonglong2 wv1 = *(const ulonglong2*)(r1 + j);
                accA[j]     = f2fma(e1A, wv1.x, f2fma(e0A, wv0.x, accA[j]));
                accA[j + 1] = f2fma(e1A, wv1.y, f2fma(e0A, wv0.y, accA[j + 1]));
                accB[j]     = f2fma(e1B, wv1.x, f2fma(e0B, wv0.x, accB[j]));
                accB[j + 1] = f2fma(e1B, wv1.y, f2fma(e0B, wv0.y, accB[j + 1]));
            }
        }
        #pragma unroll
        for (int j = 0; j < 4; j++) {
            float vA0, vA1, vB0, vB1;
            up2(accA[j], vA0, vA1); up2(accB[j], vB0, vB1);
            vA0 = fmaxf(vA0, 0.f); vA1 = fmaxf(vA1, 0.f);
            vB0 = fmaxf(vB0, 0.f); vB1 = fmaxf(vB1, 0.f);
            const float* q = dsm + OFF_W3 + (ob * 8 + 2 * j) * 3;
            crA = fmaf(vA0, q[0], fmaf(vA1, q[3], crA));
            cgA = fmaf(vA0, q[1], fmaf(vA1, q[4], cgA));
            cbA = fmaf(vA0, q[2], fmaf(vA1, q[5], cbA));
            crB = fmaf(vB0, q[0], fmaf(vB1, q[3], crB));
            cgB = fmaf(vB0, q[1], fmaf(vB1, q[4], cgB));
            cbB = fmaf(vB0, q[2], fmaf(vB1, q[5], cbB));
        }
    }

    out[pA] = make_float4(wgtA, 1.f / (1.f + expf(-crA)),
                          1.f / (1.f + expf(-cgA)), 1.f / (1.f + expf(-cbA)));
    out[pB] = make_float4(wgtB, 1.f / (1.f + expf(-crB)),
                          1.f / (1.f + expf(-cgB)), 1.f / (1.f + expf(-cbB)));
}

extern "C" void kernel_launch(void* const* d_in, const int* in_sizes, int n_in,
                              void* d_out, int out_size)
{
    const float* xyz   = (const float*)d_in[0];
    const float* delta = (const float*)d_in[1];
    const float* table = (const float*)d_in[2];
    const float* w_in  = (const float*)d_in[3];
    const float* w_out = (const float*)d_in[4];
    const float* rw1   = (const float*)d_in[5];
    const float* rw2   = (const float*)d_in[6];
    const float* rw3   = (const float*)d_in[7];
    float4* out = (float4*)d_out;

    Consts cc;
    const double scale = exp((log(4096.0) - log(16.0)) / 15.0);
    for (int l = 0; l < NLEV; l++)
        cc.res[l] = (float)floor(16.0 * pow(scale, (double)l));
    const float offset = (float)(log(log(1.0 / 0.99)) - log(6.0 - 2.0) - 0.5);

    // streams/events created once, on the (uncaptured) correctness call
    static cudaStream_t s2 = 0;
    static cudaEvent_t evC[NCHUNK], evJoin = 0;
    static int inited = 0;
    if (!inited) {
        cudaStreamCreateWithFlags(&s2, cudaStreamNonBlocking);
        cudaEventCreateWithFlags(&evJoin, cudaEventDisableTiming);
        for (int i = 0; i < NCHUNK; i++)
            cudaEventCreateWithFlags(&evC[i], cudaEventDisableTiming);
        cudaFuncSetAttribute(mlp_kernel,
                             cudaFuncAttributeMaxDynamicSharedMemorySize,
                             SMEM_BYTES);
        inited = 1;
    }

    // 2-chunk pipeline: encode chunk c+1 (gather/L1-bound, stream 0)
    // overlaps mlp chunk c (FMA-bound, s2). Launch idx 5 under ncu = m1.
    for (int c = 0; c < NCHUNK; c++) {
        encode_kernel<<<CPTS / 256, 256>>>(xyz, table, cc, c * CPTS);
        cudaEventRecord(evC[c], 0);
        cudaStreamWaitEvent(s2, evC[c], 0);
        mlp_kernel<<<CPTS / 256, 128, SMEM_BYTES, s2>>>(
            delta, w_in, w_out, rw1, rw2, rw3, out, offset, c * CPTS);
    }
    cudaEventRecord(evJoin, s2);
    cudaStreamWaitEvent(0, evJoin, 0);
}

// round 13
// speedup vs baseline: 1.7867x; 1.7867x over previous
#include <cuda_runtime.h>
#include <cuda_fp16.h>
#include <math.h>

typedef unsigned int u32;
typedef unsigned long long u64;

#define NLEV 16
#define HSIZE (1u << 19)
#define HMASK (HSIZE - 1u)
#define NPTS (4096 * 128)

struct Consts { float res[NLEV]; };

// ---------- packed f32x2 helpers ----------
__device__ __forceinline__ u64 pk2(float a, float b) {
    u64 r; asm("mov.b64 %0,{%1,%2};" : "=l"(r) : "f"(a), "f"(b)); return r;
}
__device__ __forceinline__ void up2(u64 v, float& a, float& b) {
    asm("mov.b64 {%0,%1},%2;" : "=f"(a), "=f"(b) : "l"(v));
}
__device__ __forceinline__ u64 f2fma(u64 a, u64 b, u64 c) {
    u64 d; asm("fma.rn.f32x2 %0,%1,%2,%3;" : "=l"(d) : "l"(a), "l"(b), "l"(c)); return d;
}
// half2 (u32) -> packed float2 (u64)
__device__ __forceinline__ u64 h2f2(u32 h) {
    const float2 f = __half22float2(*(const __half2*)&h);
    return pk2(f.x, f.y);
}

// smem layout in u32 words
#define OFF_WIN  0            // 2048 fp32
#define OFF_WOUT 2048         // 1024 fp32
#define OFF_W1   3072         //  960 fp32
#define OFF_W3   4032         //  192 fp32
#define OFF_W2H  4224         // 4096 half = 2048 u32 (rgb_w2 fp16)
#define OFF_EA   6272         // 128 rows x 17 u32 (enc half2 / feats fp32)
#define OFF_EB   (6272 + 128 * 17)
#define SMEM_U32 (6272 + 2 * 128 * 17)
#define SMEM_BYTES (SMEM_U32 * 4)

__global__ void __launch_bounds__(128, 4) fused_kernel(
    const float* __restrict__ xyz, const float* __restrict__ delta,
    const float* __restrict__ table,
    const float* __restrict__ w_in, const float* __restrict__ w_out,
    const float* __restrict__ rw1, const float* __restrict__ rw2,
    const float* __restrict__ rw3, float4* __restrict__ out, Consts cc,
    float offset)
{
    extern __shared__ u32 dsm[];
    __shared__ float wsumA[4], wsumB[4];
    float* dsf = (float*)dsm;
    const int t = threadIdx.x;

    // prologue: stage weights (rgb_w2 converted to fp16)
    for (int i = t; i < 2048; i += 128) dsf[OFF_WIN + i]  = w_in[i];
    for (int i = t; i < 1024; i += 128) dsf[OFF_WOUT + i] = w_out[i];
    for (int i = t; i < 960;  i += 128) dsf[OFF_W1 + i]   = rw1[i];
    for (int i = t; i < 192;  i += 128) dsf[OFF_W3 + i]   = rw3[i];
    for (int i = t; i < 4096; i += 128)
        ((half*)(dsm + OFF_W2H))[i] = __float2half_rn(rw2[i]);
    __syncthreads();

    const int pA = blockIdx.x * 256 + t;   // ray A
    const int pB = pA + 128;               // ray B
    u32* EA = dsm + OFF_EA + t * 17;       // thread-private rows (stride 17: conflict-free)
    u32* EB = dsm + OFF_EB + t * 17;

    // ================= phase 1: encode both points into smem (fp16) =========
    {
        const float pxA = __ldg(xyz + 3 * pA), pyA = __ldg(xyz + 3 * pA + 1),
                    pzA = __ldg(xyz + 3 * pA + 2);
        const float pxB = __ldg(xyz + 3 * pB), pyB = __ldg(xyz + 3 * pB + 1),
                    pzB = __ldg(xyz + 3 * pB + 2);
        #pragma unroll 1
        for (int l = 0; l < NLEV; l++) {
            const float r = cc.res[l];
            const float2* tab = (const float2*)table + (size_t)l * HSIZE;
            // issue all 16 gathers (A then B) before consuming any
            float2 tvA[8], tvB[8];
            float XA = pxA * r, YA = pyA * r, ZA = pzA * r;
            float fxA = floorf(XA), fyA = floorf(YA), fzA = floorf(ZA);
            const float axA = XA - fxA, ayA = YA - fyA, azA = ZA - fzA;
            {
                const u32 ix = (u32)fxA, iy = (u32)fyA, iz = (u32)fzA;
                const u32 hx0 = ix, hx1 = ix + 1u;
                const u32 hy0 = iy * 2654435761u, hy1 = hy0 + 2654435761u;
                const u32 hz0 = iz * 805459861u,  hz1 = hz0 + 805459861u;
                #pragma unroll
                for (int c = 0; c < 8; c++) {
                    const u32 hx = (c & 4) ? hx1 : hx0;
                    const u32 hy = (c & 2) ? hy1 : hy0;
                    const u32 hz = (c & 1) ? hz1 : hz0;
                    tvA[c] = __ldg(tab + ((hx ^ hy ^ hz) & HMASK));
                }
            }
            float XB = pxB * r, YB = pyB * r, ZB = pzB * r;
            float fxB = floorf(XB), fyB = floorf(YB), fzB = floorf(ZB);
            const float axB = XB - fxB, ayB = YB - fyB, azB = ZB - fzB;
            {
                const u32 ix = (u32)fxB, iy = (u32)fyB, iz = (u32)fzB;
                const u32 hx0 = ix, hx1 = ix + 1u;
                const u32 hy0 = iy * 2654435761u, hy1 = hy0 + 2654435761u;
                const u32 hz0 = iz * 805459861u,  hz1 = hz0 + 805459861u;
                #pragma unroll
                for (int c = 0; c < 8; c++) {
                    const u32 hx = (c & 4) ? hx1 : hx0;
                    const u32 hy = (c & 2) ? hy1 : hy0;
                    const u32 hz = (c & 1) ? hz1 : hz0;
                    tvB[c] = __ldg(tab + ((hx ^ hy ^ hz) & HMASK));
                }
            }
            const float bxA = 1.f - axA, byA = 1.f - ayA, bzA = 1.f - azA;
            float a0 = 0.f, a1 = 0.f;
            #pragma unroll
            for (int c = 0; c < 8; c++) {
                const float w = ((c & 4) ? axA : bxA) * ((c & 2) ? ayA : byA) * ((c & 1) ? azA : bzA);
                a0 = fmaf(w, tvA[c].x, a0);
                a1 = fmaf(w, tvA[c].y, a1);
            }
            __half2 hA2 = __floats2half2_rn(a0, a1);
            EA[l] = *(u32*)&hA2;

            const float bxB = 1.f - axB, byB = 1.f - ayB, bzB = 1.f - azB;
            float b0 = 0.f, b1 = 0.f;
            #pragma unroll
            for (int c = 0; c < 8; c++) {
                const float w = ((c & 4) ? axB : bxB) * ((c & 2) ? ayB : byB) * ((c & 1) ? azB : bzB);
                b0 = fmaf(w, tvB[c].x, b0);
                b1 = fmaf(w, tvB[c].y, b1);
            }
            __half2 hB2 = __floats2half2_rn(b0, b1);
            EB[l] = *(u32*)&hB2;
        }
    }
    // no barrier: rows are thread-private; warps desync naturally

    // ================= phase 2: density MLP (half-split, fp32) ==============
    u64 rA2[8], rB2[8];
    #pragma unroll
    for (int j = 0; j < 8; j++) { rA2[j] = 0ULL; rB2[j] = 0ULL; }

    #pragma unroll 1
    for (int half = 0; half < 2; half++) {
        u64 hA[16], hB[16];
        #pragma unroll
        for (int j = 0; j < 16; j++) { hA[j] = 0ULL; hB[j] = 0ULL; }

        #pragma unroll 1
        for (int l = 0; l < NLEV; l++) {
            const u64 eAp = h2f2(EA[l]);
            const u64 eBp = h2f2(EB[l]);
            float eAx, eAy, eBx, eBy;
            up2(eAp, eAx, eAy); up2(eBp, eBx, eBy);
            const u64 e0A = pk2(eAx, eAx), e1A = pk2(eAy, eAy);
            const u64 e0B = pk2(eBx, eBx), e1B = pk2(eBy, eBy);
            const u64* r0 = (const u64*)(dsf + OFF_WIN + (2 * l) * 64 + half * 32);
            const u64* r1 = r0 + 32;
            #pragma unroll
            for (int j = 0; j < 16; j += 2) {
                const ulonglong2 wv0 = *(const ulonglong2*)(r0 + j);
                const ulonglong2 wv1 = *(const ulonglong2*)(r1 + j);
                hA[j]     = f2fma(e1A, wv1.x, f2fma(e0A, wv0.x, hA[j]));
                hA[j + 1] = f2fma(e1A, wv1.y, f2fma(e0A, wv0.y, hA[j + 1]));
                hB[j]     = f2fma(e1B, wv1.x, f2fma(e0B, wv0.x, hB[j]));
                hB[j + 1] = f2fma(e1B, wv1.y, f2fma(e0B, wv0.y, hB[j + 1]));
            }
        }

        #pragma unroll
        for (int ic = 0; ic < 16; ic++) {
            float vA0, vA1, vB0, vB1;
            up2(hA[ic], vA0, vA1); up2(hB[ic], vB0, vB1);
            const u64 e0A = pk2(fmaxf(vA0, 0.f), fmaxf(vA0, 0.f));
            const u64 e1A = pk2(fmaxf(vA1, 0.f), fmaxf(vA1, 0.f));
            const u64 e0B = pk2(fmaxf(vB0, 0.f), fmaxf(vB0, 0.f));
            const u64 e1B = pk2(fmaxf(vB1, 0.f), fmaxf(vB1, 0.f));
            const u64* r0 = (const u64*)(dsf + OFF_WOUT + (half * 32 + 2 * ic) * 16);
            const u64* r1 = r0 + 8;
            #pragma unroll
            for (int j = 0; j < 8; j += 2) {
                const ulonglong2 wv0 = *(const ulonglong2*)(r0 + j);
                const ulonglong2 wv1 = *(const ulonglong2*)(r1 + j);
                rA2[j]     = f2fma(e1A, wv1.x, f2fma(e0A, wv0.x, rA2[j]));
                rA2[j + 1] = f2fma(e1A, wv1.y, f2fma(e0A, wv0.y, rA2[j + 1]));
                rB2[j]     = f2fma(e1B, wv1.x, f2fma(e0B, wv0.x, rB2[j]));
                rB2[j + 1] = f2fma(e1B, wv1.y, f2fma(e0B, wv0.y, rB2[j + 1]));
            }
        }
    }

    // unpack raw: raw[0] -> density; raw[1..15] -> feats overwrite enc rows (fp32)
    float* FA = (float*)EA;
    float* FB = (float*)EB;
    float d0A = 0.f, d0B = 0.f;
    #pragma unroll
    for (int j = 0; j < 8; j++) {
        float vA0, vA1, vB0, vB1;
        up2(rA2[j], vA0, vA1); up2(rB2[j], vB0, vB1);
        const int o = 2 * j;
        if (o == 0) { d0A = vA0; d0B = vB0; }
        else { FA[o - 1] = vA0; FB[o - 1] = vB0; }
        FA[o] = vA1; FB[o] = vB1;
    }

    // ---- volume-rendering weights: block-wide exclusive scan per ray ----
    const float ddA = expf(d0A + offset + logf(__ldg(delta + pA)));
    const float ddB = expf(d0B + offset + logf(__ldg(delta + pB)));
    float sA = ddA, sB = ddB;
    const int lane = t & 31, wid = t >> 5;
    #pragma unroll
    for (int o = 1; o < 32; o <<= 1) {
        const float vA = __shfl_up_sync(0xffffffffu, sA, o);
        const float vB = __shfl_up_sync(0xffffffffu, sB, o);
        if (lane >= o) { sA += vA; sB += vB; }
    }
    if (lane == 31) { wsumA[wid] = sA; wsumB[wid] = sB; }
    __syncthreads();
    float prefA = 0.f, prefB = 0.f;
    #pragma unroll
    for (int w = 0; w < 3; w++)
        if (wid > w) { prefA += wsumA[w]; prefB += wsumB[w]; }
    const float wgtA = (1.f - expf(-ddA)) * expf(-(prefA + sA - ddA));
    const float wgtB = (1.f - expf(-ddB)) * expf(-(prefB + sB - ddB));

    // ================= rgb MLP: per point; rgb_w2 in fp16 ===================
    #pragma unroll 1
    for (int pt = 0; pt < 2; pt++) {
        const float* F = (pt == 0) ? FA : FB;

        u64 h1[32];
        #pragma unroll
        for (int j = 0; j < 32; j++) h1[j] = 0ULL;
        #pragma unroll 1
        for (int i = 0; i < 15; i++) {
            const float f = F[i];
            const u64 e = pk2(f, f);
            const u64* row = (const u64*)(dsf + OFF_W1 + i * 64);
            #pragma unroll
            for (int j = 0; j < 32; j += 2) {
                const ulonglong2 wv = *(const ulonglong2*)(row + j);
                h1[j]     = f2fma(e, wv.x, h1[j]);
                h1[j + 1] = f2fma(e, wv.y, h1[j + 1]);
            }
        }
        #pragma unroll
        for (int j = 0; j < 32; j++) {
            float v0, v1; up2(h1[j], v0, v1);
            h1[j] = pk2(fmaxf(v0, 0.f), fmaxf(v1, 0.f));
        }

        float cr = 0.f, cg = 0.f, cb = 0.f;
        #pragma unroll 1
        for (int ob = 0; ob < 8; ob++) {
            u64 acc[4];
            #pragma unroll
            for (int j = 0; j < 4; j++) acc[j] = 0ULL;
            #pragma unroll
            for (int ic = 0; ic < 32; ic++) {
                float v0, v1; up2(h1[ic], v0, v1);
                const u64 e0 = pk2(v0, v0), e1 = pk2(v1, v1);
                // rows 2ic, 2ic+1 of fp16 w2; 8 outputs (ob*8..+8) = 4 half2 each
                const uint4 wr0 = *(const uint4*)(dsm + OFF_W2H + (2 * ic) * 32 + ob * 4);
                const uint4 wr1 = *(const uint4*)(dsm + OFF_W2H + (2 * ic + 1) * 32 + ob * 4);
                acc[0] = f2fma(e1, h2f2(wr1.x), f2fma(e0, h2f2(wr0.x), acc[0]));
                acc[1] = f2fma(e1, h2f2(wr1.y), f2fma(e0, h2f2(wr0.y), acc[1]));
                acc[2] = f2fma(e1, h2f2(wr1.z), f2fma(e0, h2f2(wr0.z), acc[2]));
                acc[3] = f2fma(e1, h2f2(wr1.w), f2fma(e0, h2f2(wr0.w), acc[3]));
            }
            #pragma unroll
            for (int j = 0; j < 4; j++) {
                float v0, v1; up2(acc[j], v0, v1);
                v0 = fmaxf(v0, 0.f); v1 = fmaxf(v1, 0.f);
                const float* q = dsf + OFF_W3 + (ob * 8 + 2 * j) * 3;
                cr = fmaf(v0, q[0], fmaf(v1, q[3], cr));
                cg = fmaf(v0, q[1], fmaf(v1, q[4], cg));
                cb = fmaf(v0, q[2], fmaf(v1, q[5], cb));
            }
        }

        const float wgt = (pt == 0) ? wgtA : wgtB;
        out[(pt == 0) ? pA : pB] =
            make_float4(wgt, 1.f / (1.f + expf(-cr)),
                        1.f / (1.f + expf(-cg)), 1.f / (1.f + expf(-cb)));
    }
}

extern "C" void kernel_launch(void* const* d_in, const int* in_sizes, int n_in,
                              void* d_out, int out_size)
{
    const float* xyz   = (const float*)d_in[0];
    const float* delta = (const float*)d_in[1];
    const float* table = (const float*)d_in[2];
    const float* w_in  = (const float*)d_in[3];
    const float* w_out = (const float*)d_in[4];
    const float* rw1   = (const float*)d_in[5];
    const float* rw2   = (const float*)d_in[6];
    const float* rw3   = (const float*)d_in[7];
    float4* out = (float4*)d_out;

    Consts cc;
    const double scale = exp((log(4096.0) - log(16.0)) / 15.0);
    for (int l = 0; l < NLEV; l++)
        cc.res[l] = (float)floor(16.0 * pow(scale, (double)l));
    const float offset = (float)(log(log(1.0 / 0.99)) - log(6.0 - 2.0) - 0.5);

    static int inited = 0;
    if (!inited) {
        cudaFuncSetAttribute(fused_kernel,
                             cudaFuncAttributeMaxDynamicSharedMemorySize,
                             SMEM_BYTES);
        inited = 1;
    }

    fused_kernel<<<NPTS / 256, 128, SMEM_BYTES>>>(
        xyz, delta, table, w_in, w_out, rw1, rw2, rw3, out, cc, offset);
}

// round 15
// speedup vs baseline: 2.2207x; 1.2429x over previous
#include <cuda_runtime.h>
#include <cuda_fp16.h>
#include <math.h>

typedef unsigned int u32;
typedef unsigned long long u64;

#define NLEV 16
#define HSIZE (1u << 19)
#define HMASK (HSIZE - 1u)
#define NPTS (4096 * 128)

struct Consts { float res[NLEV]; };

// ---------------- smem byte offsets (all 16B aligned) ----------------
#define SB_WSUM   0        // 4 f32
#define SB_W3T    16       // rgb_w3^T [3][64] f32 = 768
#define SB_WOUT0  784      // w_out col 0 [64] f32 = 256
#define SB_ACT    1040     // activations fp16: 128 rows x 64k, stride 144B
#define SB_RAW    19472    // raw f32: 128 rows x 18, stride 72B (c16=WGT, c17=DEN)
#define SB_WB1    28688    // w_in^T   [64n][32k] fp16, stride 80B
#define SB_WB2    33808    // w_out^T  [16n][64k] fp16, stride 144B
#define SB_WB3    36112    // rgb_w1^T [64n][16k] fp16, stride 48B
#define SB_WB4    39184    // rgb_w2^T [64n][64k] fp16, stride 144B
#define SMEM_BYTES 48400

__device__ __forceinline__ u32 smem_u32(const void* p) {
    u32 a;
    asm("{ .reg .u64 t; cvta.to.shared.u64 t, %1; cvt.u32.u64 %0, t; }"
        : "=r"(a) : "l"(p));
    return a;
}
__device__ __forceinline__ void ldsm_x4(u32 a[4], u32 addr) {
    asm volatile("ldmatrix.sync.aligned.m8n8.x4.shared.b16 {%0,%1,%2,%3}, [%4];"
                 : "=r"(a[0]), "=r"(a[1]), "=r"(a[2]), "=r"(a[3]) : "r"(addr));
}
__device__ __forceinline__ void ldsm_x2(u32 b[2], u32 addr) {
    asm volatile("ldmatrix.sync.aligned.m8n8.x2.shared.b16 {%0,%1}, [%2];"
                 : "=r"(b[0]), "=r"(b[1]) : "r"(addr));
}
__device__ __forceinline__ void mma16816(float d[4], const u32 a[4], const u32 b[2]) {
    asm volatile("mma.sync.aligned.m16n8k16.row.col.f32.f16.f16.f32 "
                 "{%0,%1,%2,%3},{%4,%5,%6,%7},{%8,%9},{%0,%1,%2,%3};"
                 : "+f"(d[0]), "+f"(d[1]), "+f"(d[2]), "+f"(d[3])
                 : "r"(a[0]), "r"(a[1]), "r"(a[2]), "r"(a[3]),
                   "r"(b[0]), "r"(b[1]));
}

// A fragment addresses (row-major ACT, stride 144B). m16n8k16 x4 order:
// [m0-7,k0-7],[m8-15,k0-7],[m0-7,k8-15],[m8-15,k8-15]
__device__ __forceinline__ u32 a_addr(u32 actb, int R, int mt, int ks, int lane) {
    const int sub = lane >> 3, r = lane & 7;
    return actb + (u32)((R + mt * 16 + ((sub & 1) << 3) + r) * 144
                        + ks * 32 + ((sub >> 1) << 4));
}
// B fragment addresses (col-major B == w^T stored [n][k], k-contiguous)
__device__ __forceinline__ u32 b_addr(u32 wb, int strideB, int nt, int ks, int lane) {
    const int sub = (lane >> 3) & 1, r = lane & 7;
    return wb + (u32)((nt * 8 + r) * strideB + ks * 32 + (sub << 4));
}

__device__ __forceinline__ void level_fetch(
    float px, float py, float pz, float r,
    const float2* __restrict__ tab,
    float2 tv[8], float& ax, float& ay, float& az)
{
    const float X = px * r, Y = py * r, Z = pz * r;
    const float fx = floorf(X), fy = floorf(Y), fz = floorf(Z);
    ax = X - fx; ay = Y - fy; az = Z - fz;
    const u32 ix = (u32)fx, iy = (u32)fy, iz = (u32)fz;
    const u32 hx0 = ix, hx1 = ix + 1u;
    const u32 hy0 = iy * 2654435761u, hy1 = hy0 + 2654435761u;
    const u32 hz0 = iz * 805459861u,  hz1 = hz0 + 805459861u;
    #pragma unroll
    for (int c = 0; c < 8; c++) {
        const u32 hx = (c & 4) ? hx1 : hx0;
        const u32 hy = (c & 2) ? hy1 : hy0;
        const u32 hz = (c & 1) ? hz1 : hz0;
        tv[c] = __ldg(tab + ((hx ^ hy ^ hz) & HMASK));
    }
}

__global__ void __launch_bounds__(128, 4) fused_hmma_kernel(
    const float* __restrict__ xyz, const float* __restrict__ delta,
    const float* __restrict__ table,
    const float* __restrict__ w_in, const float* __restrict__ w_out,
    const float* __restrict__ rw1, const float* __restrict__ rw2,
    const float* __restrict__ rw3, float4* __restrict__ out, Consts cc,
    float offset)
{
    extern __shared__ char smem[];
    float* dsf = (float*)smem;
    const u32 sbase = smem_u32(smem);
    const u32 actb = sbase + SB_ACT;
    const int t = threadIdx.x;
    const int lane = t & 31, wid = t >> 5;
    const int g = lane >> 2, t4 = lane & 3;
    const int R = wid * 32;

    // ---------------- prologue: stage fp16 transposed weights ----------------
    {
        half* wb1 = (half*)(smem + SB_WB1);
        half* wb2 = (half*)(smem + SB_WB2);
        half* wb3 = (half*)(smem + SB_WB3);
        half* wb4 = (half*)(smem + SB_WB4);
        for (int i = t; i < 64 * 32; i += 128) {          // WB1[n][k] = w_in[k][n]
            const int n = i >> 5, k = i & 31;
            wb1[n * 40 + k] = __float2half_rn(w_in[k * 64 + n]);
        }
        for (int i = t; i < 16 * 64; i += 128) {          // WB2[n][k] = w_out[k][n]
            const int n = i >> 6, k = i & 63;
            wb2[n * 72 + k] = __float2half_rn(w_out[k * 16 + n]);
        }
        for (int i = t; i < 64 * 16; i += 128) {          // WB3[n][k] = rgb_w1[k][n], k15=0
            const int n = i >> 4, k = i & 15;
            wb3[n * 24 + k] = (k < 15) ? __float2half_rn(rw1[k * 64 + n]) : __half(0.f);
        }
        for (int i = t; i < 64 * 64; i += 128) {          // WB4[n][k] = rgb_w2[k][n]
            const int n = i >> 6, k = i & 63;
            wb4[n * 72 + k] = __float2half_rn(rw2[k * 64 + n]);
        }
        if (t < 64) {
            #pragma unroll
            for (int c = 0; c < 3; c++)
                dsf[SB_W3T / 4 + c * 64 + t] = rw3[t * 3 + c];   // w3^T [c][n]
            dsf[SB_WOUT0 / 4 + t] = w_out[t * 16];               // w_out col 0 (fp32)
        }
    }
    __syncthreads();

    // ---------------- phase 1: encode point t -> ACT row t (fp16) -----------
    const int p = blockIdx.x * 128 + t;
    {
        const float px = __ldg(xyz + 3 * p);
        const float py = __ldg(xyz + 3 * p + 1);
        const float pz = __ldg(xyz + 3 * p + 2);
        float2 tvb[2][8];
        float fr[2][3];
        level_fetch(px, py, pz, cc.res[0], (const float2*)table,
                    tvb[0], fr[0][0], fr[0][1], fr[0][2]);
        #pragma unroll 2
        for (int l = 0; l < NLEV; l++) {
            const int cur = l & 1, nxt = cur ^ 1;
            if (l + 1 < NLEV)
                level_fetch(px, py, pz, cc.res[l + 1],
                            (const float2*)table + (size_t)(l + 1) * HSIZE,
                            tvb[nxt], fr[nxt][0], fr[nxt][1], fr[nxt][2]);
            const float ax = fr[cur][0], ay = fr[cur][1], az = fr[cur][2];
            const float bx = 1.f - ax, by = 1.f - ay, bz = 1.f - az;
            float a0 = 0.f, a1 = 0.f;
            #pragma unroll
            for (int c = 0; c < 8; c++) {
                const float w = ((c & 4) ? ax : bx) * ((c & 2) ? ay : by) * ((c & 1) ? az : bz);
                a0 = fmaf(w, tvb[cur][c].x, a0);
                a1 = fmaf(w, tvb[cur][c].y, a1);
            }
            __half2 hv = __floats2half2_rn(a0, a1);
            *(u32*)(smem + SB_ACT + t * 144 + l * 4) = *(u32*)&hv;
        }
    }
    __syncwarp();   // warp w's rows [R,R+32) now complete for warp-private GEMMs

    // ---------------- GEMM1: h = enc @ w_in  (M32/warp, N64, K32) -----------
    float accH[2][8][4];
    #pragma unroll
    for (int i = 0; i < 2; i++)
        #pragma unroll
        for (int j = 0; j < 8; j++)
            #pragma unroll
            for (int q = 0; q < 4; q++) accH[i][j][q] = 0.f;
    #pragma unroll
    for (int ks = 0; ks < 2; ks++) {
        u32 a0[4], a1[4];
        ldsm_x4(a0, a_addr(actb, R, 0, ks, lane));
        ldsm_x4(a1, a_addr(actb, R, 1, ks, lane));
        #pragma unroll
        for (int nt = 0; nt < 8; nt++) {
            u32 b[2];
            ldsm_x2(b, b_addr(sbase + SB_WB1, 80, nt, ks, lane));
            mma16816(accH[0][nt], a0, b);
            mma16816(accH[1][nt], a1, b);
        }
    }

    // density (raw col 0) scalar fp32 from h fragments + w_out col 0
    {
        float pd[2][2] = {{0.f, 0.f}, {0.f, 0.f}};
        #pragma unroll
        for (int mt = 0; mt < 2; mt++)
            #pragma unroll
            for (int nt = 0; nt < 8; nt++) {
                const int c0 = nt * 8 + 2 * t4;
                const float w0 = dsf[SB_WOUT0 / 4 + c0];
                const float w1 = dsf[SB_WOUT0 / 4 + c0 + 1];
                pd[mt][0] += fmaxf(accH[mt][nt][0], 0.f) * w0 + fmaxf(accH[mt][nt][1], 0.f) * w1;
                pd[mt][1] += fmaxf(accH[mt][nt][2], 0.f) * w0 + fmaxf(accH[mt][nt][3], 0.f) * w1;
            }
        #pragma unroll
        for (int mt = 0; mt < 2; mt++)
            #pragma unroll
            for (int j = 0; j < 2; j++) {
                pd[mt][j] += __shfl_xor_sync(0xffffffffu, pd[mt][j], 1);
                pd[mt][j] += __shfl_xor_sync(0xffffffffu, pd[mt][j], 2);
            }
        if (t4 == 0) {
            #pragma unroll
            for (int mt = 0; mt < 2; mt++) {
                const int row = R + mt * 16 + g;
                dsf[SB_RAW / 4 + row * 18 + 17] = pd[mt][0];
                dsf[SB_RAW / 4 + (row + 8) * 18 + 17] = pd[mt][1];
            }
        }
    }

    // relu(h) -> fp16 -> ACT (cols 0..63)
    #pragma unroll
    for (int mt = 0; mt < 2; mt++)
        #pragma unroll
        for (int nt = 0; nt < 8; nt++) {
            const int row = R + mt * 16 + g;
            const int cb = (nt * 8 + 2 * t4) * 2;
            __half2 x = __floats2half2_rn(fmaxf(accH[mt][nt][0], 0.f),
                                          fmaxf(accH[mt][nt][1], 0.f));
            *(u32*)(smem + SB_ACT + row * 144 + cb) = *(u32*)&x;
            __half2 y = __floats2half2_rn(fmaxf(accH[mt][nt][2], 0.f),
                                          fmaxf(accH[mt][nt][3], 0.f));
            *(u32*)(smem + SB_ACT + (row + 8) * 144 + cb) = *(u32*)&y;
        }
    __syncwarp();

    // ---------------- GEMM2: raw = relu(h) @ w_out  (N16, K64) --------------
    {
        float acc2[2][2][4];
        #pragma unroll
        for (int i = 0; i < 2; i++)
            #pragma unroll
            for (int j = 0; j < 2; j++)
                #pragma unroll
                for (int q = 0; q < 4; q++) acc2[i][j][q] = 0.f;
        #pragma unroll
        for (int ks = 0; ks < 4; ks++) {
            u32 a0[4], a1[4];
            ldsm_x4(a0, a_addr(actb, R, 0, ks, lane));
            ldsm_x4(a1, a_addr(actb, R, 1, ks, lane));
            #pragma unroll
            for (int nt = 0; nt < 2; nt++) {
                u32 b[2];
                ldsm_x2(b, b_addr(sbase + SB_WB2, 144, nt, ks, lane));
                mma16816(acc2[0][nt], a0, b);
                mma16816(acc2[1][nt], a1, b);
            }
        }
        // store raw to RAW (fp32)
        #pragma unroll
        for (int mt = 0; mt < 2; mt++)
            #pragma unroll
            for (int nt = 0; nt < 2; nt++) {
                const int row = R + mt * 16 + g;
                const int c = nt * 8 + 2 * t4;
                *(float2*)&dsf[SB_RAW / 4 + row * 18 + c] =
                    make_float2(acc2[mt][nt][0], acc2[mt][nt][1]);
                *(float2*)&dsf[SB_RAW / 4 + (row + 8) * 18 + c] =
                    make_float2(acc2[mt][nt][2], acc2[mt][nt][3]);
            }
    }
    __syncwarp();

    // feats (raw[1..15]) -> fp16 ACT row t cols 0..15 (k15 = 0)
    {
        const float* rr = dsf + SB_RAW / 4 + t * 18;
        #pragma unroll
        for (int j = 0; j < 8; j++) {
            const float lo = rr[2 * j + 1];
            const float hi = (j < 7) ? rr[2 * j + 2] : 0.f;
            __half2 hv = __floats2half2_rn(lo, hi);
            *(u32*)(smem + SB_ACT + t * 144 + j * 4) = *(u32*)&hv;
        }
    }

    // ---------------- volrend: block scan over density -----------------------
    {
        const float d0raw = dsf[SB_RAW / 4 + t * 18 + 17];
        const float dd = expf(d0raw + offset + logf(__ldg(delta + p)));
        float s = dd;
        #pragma unroll
        for (int o = 1; o < 32; o <<= 1) {
            const float v = __shfl_up_sync(0xffffffffu, s, o);
            if (lane >= o) s += v;
        }
        if (lane == 31) dsf[SB_WSUM / 4 + wid] = s;
        __syncthreads();
        float pref = 0.f;
        #pragma unroll
        for (int w = 0; w < 3; w++)
            if (wid > w) pref += dsf[SB_WSUM / 4 + w];
        const float wgt = (1.f - expf(-dd)) * expf(-(pref + s - dd));
        dsf[SB_RAW / 4 + t * 18 + 16] = wgt;
    }
    __syncwarp();

    // ---------------- GEMM3: h1 = feats @ rgb_w1  (N64, K16) ----------------
    #pragma unroll
    for (int i = 0; i < 2; i++)
        #pragma unroll
        for (int j = 0; j < 8; j++)
            #pragma unroll
            for (int q = 0; q < 4; q++) accH[i][j][q] = 0.f;
    {
        u32 a0[4], a1[4];
        ldsm_x4(a0, a_addr(actb, R, 0, 0, lane));
        ldsm_x4(a1, a_addr(actb, R, 1, 0, lane));
        #pragma unroll
        for (int nt = 0; nt < 8; nt++) {
            u32 b[2];
            ldsm_x2(b, b_addr(sbase + SB_WB3, 48, nt, 0, lane));
            mma16816(accH[0][nt], a0, b);
            mma16816(accH[1][nt], a1, b);
        }
    }
    // relu(h1) -> fp16 -> ACT cols 0..63
    #pragma unroll
    for (int mt = 0; mt < 2; mt++)
        #pragma unroll
        for (int nt = 0; nt < 8; nt++) {
            const int row = R + mt * 16 + g;
            const int cb = (nt * 8 + 2 * t4) * 2;
            __half2 x = __floats2half2_rn(fmaxf(accH[mt][nt][0], 0.f),
                                          fmaxf(accH[mt][nt][1], 0.f));
            *(u32*)(smem + SB_ACT + row * 144 + cb) = *(u32*)&x;
            __half2 y = __floats2half2_rn(fmaxf(accH[mt][nt][2], 0.f),
                                          fmaxf(accH[mt][nt][3], 0.f));
            *(u32*)(smem + SB_ACT + (row + 8) * 144 + cb) = *(u32*)&y;
        }
    __syncwarp();

    // ---------------- GEMM4: h2 = relu(h1) @ rgb_w2  (N64, K64) -------------
    #pragma unroll
    for (int i = 0; i < 2; i++)
        #pragma unroll
        for (int j = 0; j < 8; j++)
            #pragma unroll
            for (int q = 0; q < 4; q++) accH[i][j][q] = 0.f;
    #pragma unroll
    for (int ks = 0; ks < 4; ks++) {
        u32 a0[4], a1[4];
        ldsm_x4(a0, a_addr(actb, R, 0, ks, lane));
        ldsm_x4(a1, a_addr(actb, R, 1, ks, lane));
        #pragma unroll
        for (int nt = 0; nt < 8; nt++) {
            u32 b[2];
            ldsm_x2(b, b_addr(sbase + SB_WB4, 144, nt, ks, lane));
            mma16816(accH[0][nt], a0, b);
            mma16816(accH[1][nt], a1, b);
        }
    }

    // ---------------- rgb = sigmoid(relu(h2) @ rgb_w3) -----------------------
    #pragma unroll
    for (int mt = 0; mt < 2; mt++) {
        float pr0[3] = {0.f, 0.f, 0.f};   // row R+mt*16+g
        float pr1[3] = {0.f, 0.f, 0.f};   // row +8
        #pragma unroll
        for (int nt = 0; nt < 8; nt++) {
            const int c0 = nt * 8 + 2 * t4;
            const float v0 = fmaxf(accH[mt][nt][0], 0.f);
            const float v1 = fmaxf(accH[mt][nt][1], 0.f);
            const float v2 = fmaxf(accH[mt][nt][2], 0.f);
            const float v3 = fmaxf(accH[mt][nt][3], 0.f);
            #pragma unroll
            for (int c = 0; c < 3; c++) {
                const float2 wv = *(const float2*)&dsf[SB_W3T / 4 + c * 64 + c0];
                pr0[c] += v0 * wv.x + v1 * wv.y;
                pr1[c] += v2 * wv.x + v3 * wv.y;
            }
        }
        #pragma unroll
        for (int c = 0; c < 3; c++) {
            pr0[c] += __shfl_xor_sync(0xffffffffu, pr0[c], 1);
            pr0[c] += __shfl_xor_sync(0xffffffffu, pr0[c], 2);
            pr1[c] += __shfl_xor_sync(0xffffffffu, pr1[c], 1);
            pr1[c] += __shfl_xor_sync(0xffffffffu, pr1[c], 2);
        }
        if (t4 == 0) {
            const int row0 = R + mt * 16 + g;
            const float wg0 = dsf[SB_RAW / 4 + row0 * 18 + 16];
            out[blockIdx.x * 128 + row0] = make_float4(
                wg0, 1.f / (1.f + expf(-pr0[0])),
                1.f / (1.f + expf(-pr0[1])), 1.f / (1.f + expf(-pr0[2])));
            const int row1 = row0 + 8;
            const float wg1 = dsf[SB_RAW / 4 + row1 * 18 + 16];
            out[blockIdx.x * 128 + row1] = make_float4(
                wg1, 1.f / (1.f + expf(-pr1[0])),
                1.f / (1.f + expf(-pr1[1])), 1.f / (1.f + expf(-pr1[2])));
        }
    }
}

extern "C" void kernel_launch(void* const* d_in, const int* in_sizes, int n_in,
                              void* d_out, int out_size)
{
    const float* xyz   = (const float*)d_in[0];
    const float* delta = (const float*)d_in[1];
    const float* table = (const float*)d_in[2];
    const float* w_in  = (const float*)d_in[3];
    const float* w_out = (const float*)d_in[4];
    const float* rw1   = (const float*)d_in[5];
    const float* rw2   = (const float*)d_in[6];
    const float* rw3   = (const float*)d_in[7];
    float4* out = (float4*)d_out;

    Consts cc;
    const double scale = exp((log(4096.0) - log(16.0)) / 15.0);
    for (int l = 0; l < NLEV; l++)
        cc.res[l] = (float)floor(16.0 * pow(scale, (double)l));
    const float offset = (float)(log(log(1.0 / 0.99)) - log(6.0 - 2.0) - 0.5);

    static int inited = 0;
    if (!inited) {
        cudaFuncSetAttribute(fused_hmma_kernel,
                             cudaFuncAttributeMaxDynamicSharedMemorySize,
                             SMEM_BYTES);
        inited = 1;
    }

    fused_hmma_kernel<<<4096, 128, SMEM_BYTES>>>(
        xyz, delta, table, w_in, w_out, rw1, rw2, rw3, out, cc, offset);
}